// round 2
// baseline (speedup 1.0000x reference)
#include <cuda_runtime.h>
#include <cstdint>

#define N_NODES 100000
#define E_EDGES 3200000
#define F_INDIM 512
#define H_DIM   128
#define C_OUT   40

// ---------------- scratch (device globals: no runtime allocation) -------------
__device__ __align__(16) float g_h[N_NODES * H_DIM];
__device__ __align__(16) float g_tmp[N_NODES * H_DIM];
__device__ __align__(16) float g_wide[N_NODES * C_OUT];
__device__ float g_attn0[N_NODES];
__device__ float g_dinv[N_NODES];          // deg (accum) then rsqrt(deg)
__device__ int   g_counts[N_NODES];
__device__ int   g_offsets[N_NODES];
__device__ int   g_cursor[N_NODES];
__device__ int   g_csr_row[E_EDGES];
__device__ float g_csr_val[E_EDGES];
__device__ int   g_partials[32];
__device__ __align__(16) float g_Wwa[F_INDIM * 48];  // cols 0-39 Ww, 40-41 Wa, pad
__device__ float g_bwa[48];
__device__ __align__(16) float g_W2p[H_DIM * 48];    // cols 0-39 W2, pad
__device__ int   g_is64;                   // 1 if edge_index is int64, else int32

// ---------------- dtype detection ----------------
__global__ void k_detect(const unsigned* __restrict__ ei_raw) {
    // int64 values < 2^17: every odd 32-bit word == 0. int32: random nonzero.
    if (threadIdx.x == 0) g_is64 = 1;
    __syncthreads();
    unsigned v = ei_raw[2 * (threadIdx.x * 997 + 1) + 1];
    if (v != 0) atomicAnd(&g_is64, 0);
}

__device__ __forceinline__ void load_edge(const void* ei, int e, int is64,
                                          int& row, int& col) {
    if (is64) {
        const long long* p = (const long long*)ei;
        row = (int)p[e]; col = (int)p[E_EDGES + e];
    } else {
        const int* p = (const int*)ei;
        row = p[e]; col = p[E_EDGES + e];
    }
}

// ---------------- init / pack ----------------
__global__ void k_init() {
    int n = blockIdx.x * blockDim.x + threadIdx.x;
    if (n < N_NODES) { g_dinv[n] = 1.0f; g_counts[n] = 0; }
}

__global__ void k_pack(const float* __restrict__ Ww, const float* __restrict__ bw,
                       const float* __restrict__ Wa, const float* __restrict__ ba,
                       const float* __restrict__ W2) {
    int i = blockIdx.x * blockDim.x + threadIdx.x;
    if (i < F_INDIM * 48) {
        int k = i / 48, c = i % 48;
        g_Wwa[i] = (c < 40) ? Ww[k * 40 + c] : ((c < 42) ? Wa[k * 2 + (c - 40)] : 0.0f);
    }
    if (i < H_DIM * 48) {
        int k = i / 48, c = i % 48;
        g_W2p[i] = (c < 40) ? W2[k * 40 + c] : 0.0f;
    }
    if (i < 48) {
        g_bwa[i] = (i < 40) ? bw[i] : ((i < 42) ? ba[i - 40] : 0.0f);
    }
}

// ---------------- degree + CSR build ----------------
__global__ void k_edge_deg(const void* __restrict__ ei, const float* __restrict__ ew) {
    int e = blockIdx.x * blockDim.x + threadIdx.x;
    if (e >= E_EDGES) return;
    int row, col;
    load_edge(ei, e, g_is64, row, col);
    atomicAdd(&g_dinv[col], ew[e]);     // g_dinv holds deg here (init 1.0 = self loop)
    atomicAdd(&g_counts[col], 1);
}

__global__ void k_rsqrt() {
    int n = blockIdx.x * blockDim.x + threadIdx.x;
    if (n < N_NODES) g_dinv[n] = rsqrtf(g_dinv[n]);
}

// exclusive scan of g_counts -> g_offsets  (25 blocks x 256 threads x 16 items)
__global__ void k_scan1() {
    int t = threadIdx.x;
    int base = blockIdx.x * 4096 + t * 16;
    int vals[16]; int tot = 0;
#pragma unroll
    for (int i = 0; i < 16; i++) {
        int idx = base + i;
        int v = (idx < N_NODES) ? g_counts[idx] : 0;
        vals[i] = v; tot += v;
    }
    int lane = t & 31, w = t >> 5;
    int inc = tot;
#pragma unroll
    for (int o = 1; o < 32; o <<= 1) {
        int x = __shfl_up_sync(0xffffffffu, inc, o);
        if (lane >= o) inc += x;
    }
    __shared__ int wsum[8];
    __shared__ int wexc[8];
    if (lane == 31) wsum[w] = inc;
    __syncthreads();
    if (t == 0) {
        int run = 0;
        for (int i = 0; i < 8; i++) { wexc[i] = run; run += wsum[i]; }
        g_partials[blockIdx.x] = run;
    }
    __syncthreads();
    int run = wexc[w] + inc - tot;   // exclusive prefix for this thread
#pragma unroll
    for (int i = 0; i < 16; i++) {
        int idx = base + i;
        if (idx < N_NODES) g_offsets[idx] = run;
        run += vals[i];
    }
}

__global__ void k_scan2() {
    int run = 0;
    for (int b = 0; b < 25; b++) { int v = g_partials[b]; g_partials[b] = run; run += v; }
}

__global__ void k_scan3() {
    int idx = blockIdx.x * blockDim.x + threadIdx.x;
    if (idx < N_NODES) {
        int o = g_offsets[idx] + g_partials[idx / 4096];
        g_offsets[idx] = o;
        g_cursor[idx] = o;
    }
}

__global__ void k_place(const void* __restrict__ ei, const float* __restrict__ ew) {
    int e = blockIdx.x * blockDim.x + threadIdx.x;
    if (e >= E_EDGES) return;
    int row, col;
    load_edge(ei, e, g_is64, row, col);
    int p = atomicAdd(&g_cursor[col], 1);
    g_csr_row[p] = row;
    g_csr_val[p] = g_dinv[row] * ew[e] * g_dinv[col];
}

// ---------------- GEMM: [M,K] @ [K,128] -> [M,128] ----------------
__global__ __launch_bounds__(256) void gemm_n128(
    const float* __restrict__ A, const float* __restrict__ B,
    const float* __restrict__ bias, float* __restrict__ C,
    int M, int K, int relu)
{
    __shared__ float As[16][132];   // [k][m], padded
    __shared__ float Bs[16][128];
    const int tid = threadIdx.x;
    const int tx = tid & 15, ty = tid >> 4;
    const int m0 = blockIdx.x * 128;
    float acc[8][8];
#pragma unroll
    for (int i = 0; i < 8; i++)
#pragma unroll
        for (int j = 0; j < 8; j++) acc[i][j] = 0.0f;

    const int ra = tid >> 2;
    const int ca = (tid & 3) << 2;
    for (int k0 = 0; k0 < K; k0 += 16) {
#pragma unroll
        for (int i = 0; i < 2; i++) {
            int m = m0 + ra + i * 64;
            float4 v = make_float4(0.f, 0.f, 0.f, 0.f);
            if (m < M) v = *(const float4*)(A + (size_t)m * K + k0 + ca);
            As[ca + 0][ra + i * 64] = v.x;
            As[ca + 1][ra + i * 64] = v.y;
            As[ca + 2][ra + i * 64] = v.z;
            As[ca + 3][ra + i * 64] = v.w;
        }
#pragma unroll
        for (int i = 0; i < 2; i++) {
            int kk = (tid >> 5) + i * 8;
            int nn = (tid & 31) << 2;
            *(float4*)&Bs[kk][nn] = *(const float4*)(B + (size_t)(k0 + kk) * 128 + nn);
        }
        __syncthreads();
#pragma unroll
        for (int kk = 0; kk < 16; kk++) {
            float4 a0 = *(const float4*)&As[kk][ty * 8];
            float4 a1 = *(const float4*)&As[kk][ty * 8 + 4];
            float4 b0 = *(const float4*)&Bs[kk][tx * 8];
            float4 b1 = *(const float4*)&Bs[kk][tx * 8 + 4];
            float a[8] = {a0.x, a0.y, a0.z, a0.w, a1.x, a1.y, a1.z, a1.w};
            float b[8] = {b0.x, b0.y, b0.z, b0.w, b1.x, b1.y, b1.z, b1.w};
#pragma unroll
            for (int i = 0; i < 8; i++)
#pragma unroll
                for (int j = 0; j < 8; j++) acc[i][j] += a[i] * b[j];
        }
        __syncthreads();
    }
#pragma unroll
    for (int i = 0; i < 8; i++) {
        int m = m0 + ty * 8 + i;
        if (m >= M) continue;
#pragma unroll
        for (int j = 0; j < 8; j++) {
            float v = acc[i][j];
            if (bias) v += bias[tx * 8 + j];
            if (relu) v = fmaxf(v, 0.0f);
            C[(size_t)m * 128 + tx * 8 + j] = v;
        }
    }
}

// ---------------- skinny GEMM: [M,K] @ [K,48] with fused epilogues ----------------
__global__ __launch_bounds__(256) void gemm_skinny(
    const float* __restrict__ A, const float* __restrict__ Bp,
    int M, int K, int mode, const float* __restrict__ b2, float* __restrict__ out)
{
    __shared__ float As[16][68];
    __shared__ float Bs[16][48];
    const int tid = threadIdx.x;
    const int tx = tid & 15, ty = tid >> 4;
    const int m0 = blockIdx.x * 64;
    float acc[4][3];
#pragma unroll
    for (int i = 0; i < 4; i++)
#pragma unroll
        for (int j = 0; j < 3; j++) acc[i][j] = 0.0f;

    const int ra = tid >> 2;
    const int ca = (tid & 3) << 2;
    for (int k0 = 0; k0 < K; k0 += 16) {
        {
            int m = m0 + ra;
            float4 v = make_float4(0.f, 0.f, 0.f, 0.f);
            if (m < M) v = *(const float4*)(A + (size_t)m * K + k0 + ca);
            As[ca + 0][ra] = v.x; As[ca + 1][ra] = v.y;
            As[ca + 2][ra] = v.z; As[ca + 3][ra] = v.w;
        }
        if (tid < 192) {
            int kk = tid / 12;
            int nn = (tid % 12) * 4;
            *(float4*)&Bs[kk][nn] = *(const float4*)(Bp + (size_t)(k0 + kk) * 48 + nn);
        }
        __syncthreads();
#pragma unroll
        for (int kk = 0; kk < 16; kk++) {
            float a[4], b[3];
#pragma unroll
            for (int i = 0; i < 4; i++) a[i] = As[kk][ty * 4 + i];
#pragma unroll
            for (int j = 0; j < 3; j++) b[j] = Bs[kk][tx * 3 + j];
#pragma unroll
            for (int i = 0; i < 4; i++)
#pragma unroll
                for (int j = 0; j < 3; j++) acc[i][j] += a[i] * b[j];
        }
        __syncthreads();
    }
    if (mode == 0) {
#pragma unroll
        for (int i = 0; i < 4; i++) {
            int m = m0 + ty * 4 + i;
            if (m >= M) continue;
#pragma unroll
            for (int j = 0; j < 3; j++) {
                int c = tx * 3 + j;
                if (c < 40) g_wide[(size_t)m * 40 + c] = acc[i][j] + g_bwa[c];
            }
            if (tx == 13) {  // cols 39,40,41 -> acc[i][1]=logit0, acc[i][2]=logit1
                float l0 = acc[i][1] + g_bwa[40];
                float l1 = acc[i][2] + g_bwa[41];
                g_attn0[m] = 1.0f / (1.0f + expf(l1 - l0));
            }
        }
    } else {
#pragma unroll
        for (int i = 0; i < 4; i++) {
            int m = m0 + ty * 4 + i;
            if (m >= M) continue;
            float a0 = g_attn0[m];
            float a1 = 1.0f - a0;
#pragma unroll
            for (int j = 0; j < 3; j++) {
                int c = tx * 3 + j;
                if (c < 40) {
                    float deep = acc[i][j] + b2[c];
                    out[(size_t)m * 40 + c] = deep * a0 + g_wide[(size_t)m * 40 + c] * a1;
                }
            }
        }
    }
}

// ---------------- pull-mode aggregation (one warp per node, float4 lanes) ------
__global__ __launch_bounds__(256) void k_aggregate(
    const float* __restrict__ tmp, const float* __restrict__ bias,
    float* __restrict__ outH)
{
    int n = (blockIdx.x * blockDim.x + threadIdx.x) >> 5;
    int lane = threadIdx.x & 31;
    if (n >= N_NODES) return;
    float di = g_dinv[n];
    float s = di * di;
    float4 acc = ((const float4*)(tmp + (size_t)n * 128))[lane];
    acc.x *= s; acc.y *= s; acc.z *= s; acc.w *= s;
    int st = g_offsets[n];
    int en = st + g_counts[n];
    for (int p = st; p < en; p++) {
        int r = g_csr_row[p];
        float v = g_csr_val[p];
        float4 t = ((const float4*)(tmp + (size_t)r * 128))[lane];
        acc.x += v * t.x; acc.y += v * t.y; acc.z += v * t.z; acc.w += v * t.w;
    }
    float4 b = ((const float4*)bias)[lane];
    acc.x = fmaxf(acc.x + b.x, 0.0f);
    acc.y = fmaxf(acc.y + b.y, 0.0f);
    acc.z = fmaxf(acc.z + b.z, 0.0f);
    acc.w = fmaxf(acc.w + b.w, 0.0f);
    ((float4*)(outH + (size_t)n * 128))[lane] = acc;
}

// ---------------- launch ----------------
extern "C" void kernel_launch(void* const* d_in, const int* in_sizes, int n_in,
                              void* d_out, int out_size)
{
    const float* x   = (const float*)d_in[0];
    const void*  ei  = d_in[1];
    const float* ew  = (const float*)d_in[2];
    const float* W1  = (const float*)d_in[3];
    const float* b1  = (const float*)d_in[4];
    const float* Wc1 = (const float*)d_in[5];
    const float* bc1 = (const float*)d_in[6];
    const float* Wc2 = (const float*)d_in[7];
    const float* bc2 = (const float*)d_in[8];
    const float* W2  = (const float*)d_in[9];
    const float* b2  = (const float*)d_in[10];
    const float* Ww  = (const float*)d_in[11];
    const float* bw  = (const float*)d_in[12];
    const float* Wa  = (const float*)d_in[13];
    const float* ba  = (const float*)d_in[14];
    float* out = (float*)d_out;

    float *h, *tmp, *Wwa, *W2p;
    cudaGetSymbolAddress((void**)&h,   g_h);
    cudaGetSymbolAddress((void**)&tmp, g_tmp);
    cudaGetSymbolAddress((void**)&Wwa, g_Wwa);
    cudaGetSymbolAddress((void**)&W2p, g_W2p);

    const int EB = (E_EDGES + 255) / 256;          // 12500
    const int NB = (N_NODES + 255) / 256;          // 391

    k_detect<<<1, 64>>>((const unsigned*)ei);
    k_init<<<NB, 256>>>();
    k_pack<<<(F_INDIM * 48 + 255) / 256, 256>>>(Ww, bw, Wa, ba, W2);
    k_edge_deg<<<EB, 256>>>(ei, ew);
    k_rsqrt<<<NB, 256>>>();
    k_scan1<<<25, 256>>>();
    k_scan2<<<1, 1>>>();
    k_scan3<<<(N_NODES + 255) / 256, 256>>>();
    k_place<<<EB, 256>>>(ei, ew);

    // deep branch: h1 = relu(x @ W1 + b1)
    gemm_n128<<<(N_NODES + 127) / 128, 256>>>(x, W1, b1, h, N_NODES, F_INDIM, 1);
    // wide + attention logits from x
    gemm_skinny<<<(N_NODES + 63) / 64, 256>>>(x, Wwa, N_NODES, F_INDIM, 0, nullptr, nullptr);

    // conv1: tmp = h @ Wc1 ; h = relu(aggregate(tmp) + bc1)
    gemm_n128<<<(N_NODES + 127) / 128, 256>>>(h, Wc1, nullptr, tmp, N_NODES, H_DIM, 0);
    k_aggregate<<<(N_NODES * 32 + 255) / 256, 256>>>(tmp, bc1, h);

    // conv2
    gemm_n128<<<(N_NODES + 127) / 128, 256>>>(h, Wc2, nullptr, tmp, N_NODES, H_DIM, 0);
    k_aggregate<<<(N_NODES * 32 + 255) / 256, 256>>>(tmp, bc2, h);

    // final: deep = h @ W2 + b2 ; out = deep*a0 + wide*(1-a0)
    gemm_skinny<<<(N_NODES + 63) / 64, 256>>>(h, W2p, N_NODES, H_DIM, 1, b2, out);
}